// round 1
// baseline (speedup 1.0000x reference)
#include <cuda_runtime.h>
#include <math.h>

// ---------------------------------------------------------------------------
// RGCN, 2 layers. Restructured as:
//   agg[n][r*64+d] = mean_{e: type r, dst n} x[src(e)][d]   (scatter w/ folded 1/cnt)
//   h1 = relu(agg @ W1cat + x @ root1 + b1)
//   agg2 likewise from h1
//   out = log_softmax(relu(agg2 @ W2cat + h1 @ root2 + b2))
// ---------------------------------------------------------------------------

namespace {
constexpr int N_NODES = 100000;
constexpr int R = 16;
constexpr int D = 64;
constexpr int KBIG = R * D;  // 1024
}

// Static scratch (allocation-free rule): ~448 MB total.
__device__ int   g_cnt[R * N_NODES];
__device__ float g_inv[R * N_NODES];
__device__ float g_agg[(size_t)N_NODES * KBIG];
__device__ float g_h1[(size_t)N_NODES * D];

// ---------------------------------------------------------------------------
__global__ void k_zero_cnt() {
    int i = blockIdx.x * blockDim.x + threadIdx.x;
    if (i < R * N_NODES) g_cnt[i] = 0;
}

__global__ void k_count(const int* __restrict__ dst, const int* __restrict__ et, int E) {
    int i = blockIdx.x * blockDim.x + threadIdx.x;
    if (i < E) atomicAdd(&g_cnt[et[i] * N_NODES + dst[i]], 1);
}

__global__ void k_inv() {
    int i = blockIdx.x * blockDim.x + threadIdx.x;
    if (i < R * N_NODES) {
        int c = g_cnt[i];
        g_inv[i] = 1.0f / (float)(c > 0 ? c : 1);
    }
}

__global__ void k_zero_agg() {
    size_t i = (size_t)blockIdx.x * blockDim.x + threadIdx.x;
    size_t n4 = (size_t)N_NODES * KBIG / 4;
    if (i < n4) {
        reinterpret_cast<float4*>(g_agg)[i] = make_float4(0.f, 0.f, 0.f, 0.f);
    }
}

// 128-bit reduction to global (sm_90+): one RED lane per 4 floats.
__device__ __forceinline__ void red_add_v4(float* addr, float4 v) {
    asm volatile("red.global.add.v4.f32 [%0], {%1, %2, %3, %4};"
                 :: "l"(addr), "f"(v.x), "f"(v.y), "f"(v.z), "f"(v.w)
                 : "memory");
}

// 16 threads per edge; each handles one float4 of the 64-float source row.
__global__ void k_scatter(const float* __restrict__ feat, int use_h1,
                          const int* __restrict__ src,
                          const int* __restrict__ dst,
                          const int* __restrict__ et, int E) {
    long long gid = (long long)blockIdx.x * blockDim.x + threadIdx.x;
    int e = (int)(gid >> 4);
    int lane = (int)(gid & 15);
    if (e >= E) return;
    const float* f = use_h1 ? (const float*)g_h1 : feat;
    int s = src[e], d = dst[e], r = et[e];
    float w = g_inv[r * N_NODES + d];
    float4 v = reinterpret_cast<const float4*>(f)[(size_t)s * 16 + lane];
    float4 vw = make_float4(v.x * w, v.y * w, v.z * w, v.w * w);
    red_add_v4(&g_agg[((size_t)d * R + r) * D + (size_t)lane * 4], vw);
}

// ---------------------------------------------------------------------------
// GEMM1: h1 = relu(agg(N x 1024) @ W1(1024 x 64) + x(N x 64) @ root1(64 x 64) + b1)
// Tiled fp32: BM=64, BN=64, BK=32, 256 threads, 4x4 microtile.
// ---------------------------------------------------------------------------
__global__ void __launch_bounds__(256) k_gemm1(const float* __restrict__ xin,
                                               const float* __restrict__ W1,
                                               const float* __restrict__ root1,
                                               const float* __restrict__ b1) {
    constexpr int BM = 64, BK = 32;
    __shared__ float As[BM][BK + 1];
    __shared__ float Bs[BK][64];
    int tid = threadIdx.x;
    int rowBase = blockIdx.x * BM;
    int row0 = (tid >> 4) * 4;
    int col0 = (tid & 15) * 4;
    float acc[4][4] = {};
    const int nTiles = (KBIG + D) / BK;  // 34
    for (int kt = 0; kt < nTiles; ++kt) {
        int k0 = kt * BK;
        bool fa = k0 < KBIG;
#pragma unroll
        for (int i = 0; i < 8; ++i) {
            int idx = tid + i * 256;
            int rr = idx >> 5, kk = idx & 31;
            int row = rowBase + rr;
            float v = 0.f;
            if (row < N_NODES)
                v = fa ? g_agg[(size_t)row * KBIG + k0 + kk]
                       : xin[(size_t)row * D + (k0 - KBIG) + kk];
            As[rr][kk] = v;
        }
#pragma unroll
        for (int i = 0; i < 8; ++i) {
            int idx = tid + i * 256;
            int kk = idx >> 6, c = idx & 63;
            Bs[kk][c] = fa ? W1[(size_t)(k0 + kk) * 64 + c]
                           : root1[(size_t)(k0 - KBIG + kk) * 64 + c];
        }
        __syncthreads();
#pragma unroll
        for (int kk = 0; kk < BK; ++kk) {
            float a[4];
#pragma unroll
            for (int i = 0; i < 4; ++i) a[i] = As[row0 + i][kk];
            float4 b = *reinterpret_cast<const float4*>(&Bs[kk][col0]);
            float bb[4] = {b.x, b.y, b.z, b.w};
#pragma unroll
            for (int i = 0; i < 4; ++i)
#pragma unroll
                for (int j = 0; j < 4; ++j)
                    acc[i][j] += a[i] * bb[j];
        }
        __syncthreads();
    }
#pragma unroll
    for (int i = 0; i < 4; ++i) {
        int row = rowBase + row0 + i;
        if (row < N_NODES) {
#pragma unroll
            for (int j = 0; j < 4; ++j) {
                float v = acc[i][j] + b1[col0 + j];
                g_h1[(size_t)row * D + col0 + j] = v > 0.f ? v : 0.f;
            }
        }
    }
}

// ---------------------------------------------------------------------------
// GEMM2 + relu + log_softmax:
// out = log_softmax(relu(agg(N x 1024) @ W2(1024 x 16) + h1 @ root2(64 x 16) + b2))
// BM=64, BN=16, BK=32, 256 threads; thread owns (1 row, 4 cols); row reduction
// via shfl within lane-quads.
// ---------------------------------------------------------------------------
__global__ void __launch_bounds__(256) k_gemm2(const float* __restrict__ W2,
                                               const float* __restrict__ root2,
                                               const float* __restrict__ b2,
                                               float* __restrict__ out) {
    constexpr int BM = 64, BK = 32, BN = 16;
    __shared__ float As[BM][BK + 1];
    __shared__ float Bs[BK][BN];
    int tid = threadIdx.x;
    int rowBase = blockIdx.x * BM;
    int rloc = tid >> 2;
    int cg = tid & 3;
    float acc[4] = {};
    const int nTiles = (KBIG + D) / BK;
    for (int kt = 0; kt < nTiles; ++kt) {
        int k0 = kt * BK;
        bool fa = k0 < KBIG;
#pragma unroll
        for (int i = 0; i < 8; ++i) {
            int idx = tid + i * 256;
            int rr = idx >> 5, kk = idx & 31;
            int row = rowBase + rr;
            float v = 0.f;
            if (row < N_NODES)
                v = fa ? g_agg[(size_t)row * KBIG + k0 + kk]
                       : g_h1[(size_t)row * D + (k0 - KBIG) + kk];
            As[rr][kk] = v;
        }
#pragma unroll
        for (int i = 0; i < 2; ++i) {
            int idx = tid + i * 256;
            int kk = idx >> 4, c = idx & 15;
            Bs[kk][c] = fa ? W2[(size_t)(k0 + kk) * BN + c]
                           : root2[(size_t)(k0 - KBIG + kk) * BN + c];
        }
        __syncthreads();
#pragma unroll
        for (int kk = 0; kk < BK; ++kk) {
            float a = As[rloc][kk];
            float4 b = *reinterpret_cast<const float4*>(&Bs[kk][cg * 4]);
            acc[0] += a * b.x;
            acc[1] += a * b.y;
            acc[2] += a * b.z;
            acc[3] += a * b.w;
        }
        __syncthreads();
    }
    // epilogue: relu then log_softmax across the 16 cols of this row
    float v[4], m = -1e30f;
#pragma unroll
    for (int j = 0; j < 4; ++j) {
        float t = acc[j] + b2[cg * 4 + j];
        v[j] = t > 0.f ? t : 0.f;
        m = fmaxf(m, v[j]);
    }
    m = fmaxf(m, __shfl_xor_sync(0xffffffffu, m, 1));
    m = fmaxf(m, __shfl_xor_sync(0xffffffffu, m, 2));
    float s = 0.f;
#pragma unroll
    for (int j = 0; j < 4; ++j) s += expf(v[j] - m);
    s += __shfl_xor_sync(0xffffffffu, s, 1);
    s += __shfl_xor_sync(0xffffffffu, s, 2);
    float ls = logf(s);
    int row = rowBase + rloc;
    if (row < N_NODES) {
#pragma unroll
        for (int j = 0; j < 4; ++j)
            out[(size_t)row * BN + cg * 4 + j] = v[j] - m - ls;
    }
}

// ---------------------------------------------------------------------------
extern "C" void kernel_launch(void* const* d_in, const int* in_sizes, int n_in,
                              void* d_out, int out_size) {
    const float* x     = (const float*)d_in[0];
    const int*   ei    = (const int*)d_in[1];
    const int*   et    = (const int*)d_in[2];
    const float* W1    = (const float*)d_in[3];
    const float* root1 = (const float*)d_in[4];
    const float* b1    = (const float*)d_in[5];
    const float* W2    = (const float*)d_in[6];
    const float* root2 = (const float*)d_in[7];
    const float* b2    = (const float*)d_in[8];
    float* out = (float*)d_out;

    const int E = in_sizes[2];
    const int* src = ei;
    const int* dst = ei + E;

    const int t = 256;
    const int gRN = (R * N_NODES + t - 1) / t;
    const size_t aggN4 = (size_t)N_NODES * KBIG / 4;
    const int gZ = (int)((aggN4 + t - 1) / t);
    const int gS = (int)(((long long)E * 16 + t - 1) / t);
    const int gM = (N_NODES + 63) / 64;

    // counts + inverse (shared by both layers)
    k_zero_cnt<<<gRN, t>>>();
    k_count<<<(E + t - 1) / t, t>>>(dst, et, E);
    k_inv<<<gRN, t>>>();

    // layer 1
    k_zero_agg<<<gZ, t>>>();
    k_scatter<<<gS, t>>>(x, 0, src, dst, et, E);
    k_gemm1<<<gM, t>>>(x, W1, root1, b1);

    // layer 2
    k_zero_agg<<<gZ, t>>>();
    k_scatter<<<gS, t>>>(nullptr, 1, src, dst, et, E);
    k_gemm2<<<gM, t>>>(W2, root2, b2, out);
}

// round 7
// speedup vs baseline: 1.4147x; 1.4147x over previous
#include <cuda_runtime.h>
#include <math.h>
#include <stdint.h>

// ---------------------------------------------------------------------------
// RGCN, 2 layers. R1 skeleton (proven to pass the memory guard) with the two
// GEMM kernels upgraded from SIMT fp32 to 3xTF32 tensor-core mma:
//   agg[n][r*64+d] = mean_{e: type r, dst n} x[src(e)][d]   (scatter w/ 1/cnt)
//   h1 = relu(agg @ W1cat + x @ root1 + b1)
//   agg2 likewise from h1
//   out = log_softmax(relu(agg2 @ W2cat + h1 @ root2 + b2))  (fused epilogue)
// Statics identical to R1: g_cnt, g_inv, g_agg, g_h1 (448 MB total).
// ---------------------------------------------------------------------------

namespace {
constexpr int N_NODES = 100000;
constexpr int R = 16;
constexpr int D = 64;
constexpr int KBIG = R * D;  // 1024
}

__device__ int   g_cnt[R * N_NODES];
__device__ float g_inv[R * N_NODES];
__device__ float g_agg[(size_t)N_NODES * KBIG];
__device__ float g_h1[(size_t)N_NODES * D];

// ---------------------------------------------------------------------------
__global__ void k_zero_cnt() {
    int i = blockIdx.x * blockDim.x + threadIdx.x;
    if (i < R * N_NODES) g_cnt[i] = 0;
}

__global__ void k_count(const int* __restrict__ dst, const int* __restrict__ et, int E) {
    int i = blockIdx.x * blockDim.x + threadIdx.x;
    if (i < E) atomicAdd(&g_cnt[et[i] * N_NODES + dst[i]], 1);
}

__global__ void k_inv() {
    int i = blockIdx.x * blockDim.x + threadIdx.x;
    if (i < R * N_NODES) {
        int c = g_cnt[i];
        g_inv[i] = 1.0f / (float)(c > 0 ? c : 1);
    }
}

__global__ void k_zero_agg() {
    size_t i = (size_t)blockIdx.x * blockDim.x + threadIdx.x;
    size_t n4 = (size_t)N_NODES * KBIG / 4;
    if (i < n4) {
        reinterpret_cast<float4*>(g_agg)[i] = make_float4(0.f, 0.f, 0.f, 0.f);
    }
}

// 128-bit reduction to global (sm_90+): one RED lane per 4 floats.
__device__ __forceinline__ void red_add_v4(float* addr, float4 v) {
    asm volatile("red.global.add.v4.f32 [%0], {%1, %2, %3, %4};"
                 :: "l"(addr), "f"(v.x), "f"(v.y), "f"(v.z), "f"(v.w)
                 : "memory");
}

// 16 threads per edge; each handles one float4 of the 64-float source row.
__global__ void k_scatter(const float* __restrict__ feat, int use_h1,
                          const int* __restrict__ src,
                          const int* __restrict__ dst,
                          const int* __restrict__ et, int E) {
    long long gid = (long long)blockIdx.x * blockDim.x + threadIdx.x;
    int e = (int)(gid >> 4);
    int lane = (int)(gid & 15);
    if (e >= E) return;
    const float* f = use_h1 ? (const float*)g_h1 : feat;
    int s = src[e], d = dst[e], r = et[e];
    float w = g_inv[r * N_NODES + d];
    float4 v = reinterpret_cast<const float4*>(f)[(size_t)s * 16 + lane];
    float4 vw = make_float4(v.x * w, v.y * w, v.z * w, v.w * w);
    red_add_v4(&g_agg[((size_t)d * R + r) * D + (size_t)lane * 4], vw);
}

// ---------------------------------------------------------------------------
// 3xTF32 mma helpers.
// ---------------------------------------------------------------------------
__device__ __forceinline__ uint32_t f2tf32(float v) {
    uint32_t r;
    asm("cvt.rna.tf32.f32 %0, %1;" : "=r"(r) : "f"(v));
    return r;
}
__device__ __forceinline__ void mma_tf32(float* c, const uint32_t* a, const uint32_t* b) {
    asm volatile(
        "mma.sync.aligned.m16n8k8.row.col.f32.tf32.tf32.f32 "
        "{%0,%1,%2,%3}, {%4,%5,%6,%7}, {%8,%9}, {%0,%1,%2,%3};"
        : "+f"(c[0]), "+f"(c[1]), "+f"(c[2]), "+f"(c[3])
        : "r"(a[0]), "r"(a[1]), "r"(a[2]), "r"(a[3]), "r"(b[0]), "r"(b[1]));
}

// ---------------------------------------------------------------------------
// GEMM1: h1 = relu(agg(N x 1024) @ W1cat + x(N x 64) @ root1 + b1)
// BM=64, BN=64, K in 17 chunks of 64 (16 from agg, 1 from x/root1).
// 256 threads, 8 warps (4m x 2n), warp tile 16x32. 3xTF32 in registers.
// ---------------------------------------------------------------------------
namespace {
constexpr int SA1 = 68;   // A smem stride (floats): conflict-free frag loads
constexpr int SB1 = 72;   // B smem stride
}

__global__ void __launch_bounds__(256) k_gemm1(const float* __restrict__ xin,
                                               const float* __restrict__ W1,
                                               const float* __restrict__ root1,
                                               const float* __restrict__ b1) {
    __shared__ float Af[64 * SA1];   // 17.4 KB
    __shared__ float Bf[64 * SB1];   // 18.4 KB
    const int tid = threadIdx.x;
    const int rb = blockIdx.x;
    const int wid = tid >> 5, lane = tid & 31;
    const int g = lane >> 2, tg = lane & 3;
    const int wm = (wid & 3) * 16;
    const int wn = (wid >> 2) * 32;

    float acc[4][4];
#pragma unroll
    for (int nt = 0; nt < 4; ++nt)
#pragma unroll
        for (int q = 0; q < 4; ++q) acc[nt][q] = 0.f;

    for (int kt = 0; kt < 17; ++kt) {
        // ---- load A chunk (64 rows x 64 k) ----
#pragma unroll
        for (int i = 0; i < 4; ++i) {
            int idx = tid + i * 256;          // float4 index
            int row = idx >> 4, c4 = idx & 15;
            int grow = rb * 64 + row;
            float4 v = make_float4(0.f, 0.f, 0.f, 0.f);
            if (grow < N_NODES) {
                v = (kt < 16)
                    ? *reinterpret_cast<const float4*>(
                          &g_agg[(size_t)grow * KBIG + kt * 64 + c4 * 4])
                    : reinterpret_cast<const float4*>(xin)[(size_t)grow * 16 + c4];
            }
            *reinterpret_cast<float4*>(&Af[row * SA1 + c4 * 4]) = v;
        }
        // ---- load B chunk (64 k x 64 cols): W1[kt] or root1 ----
        const float* bsrc = (kt < 16) ? (W1 + (size_t)kt * 64 * 64) : root1;
#pragma unroll
        for (int i = 0; i < 4; ++i) {
            int idx = tid + i * 256;
            int kk = idx >> 4, c4 = idx & 15;
            *reinterpret_cast<float4*>(&Bf[kk * SB1 + c4 * 4]) =
                reinterpret_cast<const float4*>(bsrc)[(size_t)kk * 16 + c4];
        }
        __syncthreads();

#pragma unroll
        for (int ks = 0; ks < 8; ++ks) {
            const int k0 = ks * 8;
            float a0 = Af[(wm + g)     * SA1 + k0 + tg];
            float a1 = Af[(wm + g + 8) * SA1 + k0 + tg];
            float a2 = Af[(wm + g)     * SA1 + k0 + tg + 4];
            float a3 = Af[(wm + g + 8) * SA1 + k0 + tg + 4];
            uint32_t ah[4], al[4];
            ah[0] = f2tf32(a0); al[0] = __float_as_uint(a0 - __uint_as_float(ah[0]));
            ah[1] = f2tf32(a1); al[1] = __float_as_uint(a1 - __uint_as_float(ah[1]));
            ah[2] = f2tf32(a2); al[2] = __float_as_uint(a2 - __uint_as_float(ah[2]));
            ah[3] = f2tf32(a3); al[3] = __float_as_uint(a3 - __uint_as_float(ah[3]));
            uint32_t bh[4][2], bl[4][2];
#pragma unroll
            for (int nt = 0; nt < 4; ++nt) {
                int c0 = wn + nt * 8 + g;
                float b0 = Bf[(k0 + tg)     * SB1 + c0];
                float b1v = Bf[(k0 + tg + 4) * SB1 + c0];
                bh[nt][0] = f2tf32(b0);
                bl[nt][0] = __float_as_uint(b0 - __uint_as_float(bh[nt][0]));
                bh[nt][1] = f2tf32(b1v);
                bl[nt][1] = __float_as_uint(b1v - __uint_as_float(bh[nt][1]));
            }
#pragma unroll
            for (int nt = 0; nt < 4; ++nt) {
                mma_tf32(acc[nt], ah, bh[nt]);   // hi*hi
                mma_tf32(acc[nt], ah, bl[nt]);   // hi*lo
                mma_tf32(acc[nt], al, bh[nt]);   // lo*hi
            }
        }
        __syncthreads();
    }

    // ---- epilogue: +bias, relu, store h1 ----
#pragma unroll
    for (int nt = 0; nt < 4; ++nt) {
        int col = wn + nt * 8 + 2 * tg;
        int r0 = rb * 64 + wm + g;
        int r1 = r0 + 8;
        float bx = b1[col], by = b1[col + 1];
        if (r0 < N_NODES) {
            float2 v = make_float2(fmaxf(acc[nt][0] + bx, 0.f),
                                   fmaxf(acc[nt][1] + by, 0.f));
            *reinterpret_cast<float2*>(&g_h1[(size_t)r0 * D + col]) = v;
        }
        if (r1 < N_NODES) {
            float2 v = make_float2(fmaxf(acc[nt][2] + bx, 0.f),
                                   fmaxf(acc[nt][3] + by, 0.f));
            *reinterpret_cast<float2*>(&g_h1[(size_t)r1 * D + col]) = v;
        }
    }
}

// ---------------------------------------------------------------------------
// GEMM2 + relu + log_softmax:
// out = log_softmax(relu(agg(N x 1024) @ W2cat + h1 @ root2 + b2))
// BM=128, BN=16. 8 warps, each warp owns 16 rows x 16 cols (2 n-frags).
// ---------------------------------------------------------------------------
namespace {
constexpr int SA2 = 68;
constexpr int SB2 = 24;   // 24 % 32 pattern -> conflict-free b-frag loads
}

__global__ void __launch_bounds__(256) k_gemm2(const float* __restrict__ W2,
                                               const float* __restrict__ root2,
                                               const float* __restrict__ b2,
                                               float* __restrict__ out) {
    __shared__ float Af[128 * SA2];  // 34.8 KB
    __shared__ float Bf[64 * SB2];   // 6.1 KB
    const int tid = threadIdx.x;
    const int rb = blockIdx.x;
    const int wid = tid >> 5, lane = tid & 31;
    const int g = lane >> 2, tg = lane & 3;

    float acc[2][4];
#pragma unroll
    for (int nt = 0; nt < 2; ++nt)
#pragma unroll
        for (int q = 0; q < 4; ++q) acc[nt][q] = 0.f;

    for (int kt = 0; kt < 17; ++kt) {
        // ---- load A chunk (128 rows x 64 k): agg or h1 ----
#pragma unroll
        for (int i = 0; i < 8; ++i) {
            int idx = tid + i * 256;
            int row = idx >> 4, c4 = idx & 15;
            int grow = rb * 128 + row;
            float4 v = make_float4(0.f, 0.f, 0.f, 0.f);
            if (grow < N_NODES) {
                v = (kt < 16)
                    ? *reinterpret_cast<const float4*>(
                          &g_agg[(size_t)grow * KBIG + kt * 64 + c4 * 4])
                    : reinterpret_cast<const float4*>(g_h1)[(size_t)grow * 16 + c4];
            }
            *reinterpret_cast<float4*>(&Af[row * SA2 + c4 * 4]) = v;
        }
        // ---- load B chunk (64 k x 16 cols): W2[kt] or root2 ----
        const float* bsrc = (kt < 16) ? (W2 + (size_t)kt * 64 * 16) : root2;
        {
            int kk = tid >> 2, c4 = tid & 3;   // 64 rows x 4 float4
            *reinterpret_cast<float4*>(&Bf[kk * SB2 + c4 * 4]) =
                reinterpret_cast<const float4*>(bsrc)[(size_t)kk * 4 + c4];
        }
        __syncthreads();

#pragma unroll
        for (int ks = 0; ks < 8; ++ks) {
            const int k0 = ks * 8;
            float a0 = Af[(wid * 16 + g)     * SA2 + k0 + tg];
            float a1 = Af[(wid * 16 + g + 8) * SA2 + k0 + tg];
            float a2 = Af[(wid * 16 + g)     * SA2 + k0 + tg + 4];
            float a3 = Af[(wid * 16 + g + 8) * SA2 + k0 + tg + 4];
            uint32_t ah[4], al[4];
            ah[0] = f2tf32(a0); al[0] = __float_as_uint(a0 - __uint_as_float(ah[0]));
            ah[1] = f2tf32(a1); al[1] = __float_as_uint(a1 - __uint_as_float(ah[1]));
            ah[2] = f2tf32(a2); al[2] = __float_as_uint(a2 - __uint_as_float(ah[2]));
            ah[3] = f2tf32(a3); al[3] = __float_as_uint(a3 - __uint_as_float(ah[3]));
            uint32_t bh[2][2], bl[2][2];
#pragma unroll
            for (int nt = 0; nt < 2; ++nt) {
                int c0 = nt * 8 + g;
                float b0 = Bf[(k0 + tg)     * SB2 + c0];
                float b1v = Bf[(k0 + tg + 4) * SB2 + c0];
                bh[nt][0] = f2tf32(b0);
                bl[nt][0] = __float_as_uint(b0 - __uint_as_float(bh[nt][0]));
                bh[nt][1] = f2tf32(b1v);
                bl[nt][1] = __float_as_uint(b1v - __uint_as_float(bh[nt][1]));
            }
#pragma unroll
            for (int nt = 0; nt < 2; ++nt) {
                mma_tf32(acc[nt], ah, bh[nt]);
                mma_tf32(acc[nt], ah, bl[nt]);
                mma_tf32(acc[nt], al, bh[nt]);
            }
        }
        __syncthreads();
    }

    // ---- epilogue: +bias, relu, log_softmax over 16 cols (quad shuffle) ----
    float bx0 = b2[2 * tg],     by0 = b2[2 * tg + 1];
    float bx1 = b2[8 + 2 * tg], by1 = b2[8 + 2 * tg + 1];
#pragma unroll
    for (int half = 0; half < 2; ++half) {
        // half 0 -> row wid*16+g (acc[..][0..1]); half 1 -> +8 (acc[..][2..3])
        int row = rb * 128 + wid * 16 + g + half * 8;
        float v0 = fmaxf(acc[0][half * 2 + 0] + bx0, 0.f);
        float v1 = fmaxf(acc[0][half * 2 + 1] + by0, 0.f);
        float v2 = fmaxf(acc[1][half * 2 + 0] + bx1, 0.f);
        float v3 = fmaxf(acc[1][half * 2 + 1] + by1, 0.f);
        float m = fmaxf(fmaxf(v0, v1), fmaxf(v2, v3));
        m = fmaxf(m, __shfl_xor_sync(0xffffffffu, m, 1));
        m = fmaxf(m, __shfl_xor_sync(0xffffffffu, m, 2));
        float s = expf(v0 - m) + expf(v1 - m) + expf(v2 - m) + expf(v3 - m);
        s += __shfl_xor_sync(0xffffffffu, s, 1);
        s += __shfl_xor_sync(0xffffffffu, s, 2);
        float ls = m + logf(s);
        if (row < N_NODES) {
            *reinterpret_cast<float2*>(&out[(size_t)row * 16 + 2 * tg]) =
                make_float2(v0 - ls, v1 - ls);
            *reinterpret_cast<float2*>(&out[(size_t)row * 16 + 8 + 2 * tg]) =
                make_float2(v2 - ls, v3 - ls);
        }
    }
}

// ---------------------------------------------------------------------------
extern "C" void kernel_launch(void* const* d_in, const int* in_sizes, int n_in,
                              void* d_out, int out_size) {
    const float* x     = (const float*)d_in[0];
    const int*   ei    = (const int*)d_in[1];
    const int*   et    = (const int*)d_in[2];
    const float* W1    = (const float*)d_in[3];
    const float* root1 = (const float*)d_in[4];
    const float* b1    = (const float*)d_in[5];
    const float* W2    = (const float*)d_in[6];
    const float* root2 = (const float*)d_in[7];
    const float* b2    = (const float*)d_in[8];
    float* out = (float*)d_out;

    const int E = in_sizes[2];
    const int* src = ei;
    const int* dst = ei + E;

    const int t = 256;
    const int gRN = (R * N_NODES + t - 1) / t;
    const size_t aggN4 = (size_t)N_NODES * KBIG / 4;
    const int gZ = (int)((aggN4 + t - 1) / t);
    const int gS = (int)(((long long)E * 16 + t - 1) / t);
    const int gM1 = (N_NODES + 63) / 64;
    const int gM2 = (N_NODES + 127) / 128;

    // counts + inverse (shared by both layers)
    k_zero_cnt<<<gRN, t>>>();
    k_count<<<(E + t - 1) / t, t>>>(dst, et, E);
    k_inv<<<gRN, t>>>();

    // layer 1
    k_zero_agg<<<gZ, t>>>();
    k_scatter<<<gS, t>>>(x, 0, src, dst, et, E);
    k_gemm1<<<gM1, t>>>(x, W1, root1, b1);

    // layer 2
    k_zero_agg<<<gZ, t>>>();
    k_scatter<<<gS, t>>>(nullptr, 1, src, dst, et, E);
    k_gemm2<<<gM2, t>>>(W2, root2, b2, out);
}

// round 10
// speedup vs baseline: 1.7563x; 1.2415x over previous
#include <cuda_runtime.h>
#include <math.h>
#include <stdint.h>

// ---------------------------------------------------------------------------
// RGCN 2-layer, gather-side restructuring.
// HARD RULE (empirical, 9 rounds of memory-guard evidence): __device__ globals
// must NEVER be referenced from host code (not even as kernel arguments).
// All global-buffer binding happens inside device code.
//
//   [h1 | xw] = x @ [root1 | W1cat] (+b1)    (3xTF32 mma GEMM; xw -> g_agg)
//   h1[dst]  += xw[src, r] * inv[r,dst]      (RED.v4 into L2-resident g_h1)
//   [oacc | hw] = relu(h1) @ [root2 | W2cat] (+b2)  (oacc -> g_cnt storage)
//   oacc[dst] += hw[src, r] * inv[r,dst]     (RED.v4 into L2-resident oacc)
//   d_out = log_softmax(relu(oacc))          (plain stores, k_final only)
// ---------------------------------------------------------------------------

namespace {
constexpr int N_NODES = 100000;
constexpr int R = 16;
constexpr int D = 64;
constexpr int KBIG = R * D;  // 1024
}

__device__ int   g_cnt[R * N_NODES];
__device__ float g_inv[R * N_NODES];
__device__ float g_agg[(size_t)N_NODES * KBIG];
__device__ float g_h1[(size_t)N_NODES * D];

// ---------------------------------------------------------------------------
__global__ void k_zero_cnt() {
    int i = blockIdx.x * blockDim.x + threadIdx.x;
    if (i < R * N_NODES) g_cnt[i] = 0;
}

__global__ void k_count(const int* __restrict__ dst, const int* __restrict__ et, int E) {
    int i = blockIdx.x * blockDim.x + threadIdx.x;
    if (i < E) atomicAdd(&g_cnt[et[i] * N_NODES + dst[i]], 1);
}

__global__ void k_inv() {
    int i = blockIdx.x * blockDim.x + threadIdx.x;
    if (i < R * N_NODES) {
        int c = g_cnt[i];
        g_inv[i] = 1.0f / (float)(c > 0 ? c : 1);
    }
}

// ---------------------------------------------------------------------------
// 3xTF32 mma helpers.
// ---------------------------------------------------------------------------
__device__ __forceinline__ uint32_t f2tf32(float v) {
    uint32_t r;
    asm("cvt.rna.tf32.f32 %0, %1;" : "=r"(r) : "f"(v));
    return r;
}
__device__ __forceinline__ void mma_tf32(float* c, const uint32_t* a, const uint32_t* b) {
    asm volatile(
        "mma.sync.aligned.m16n8k8.row.col.f32.tf32.tf32.f32 "
        "{%0,%1,%2,%3}, {%4,%5,%6,%7}, {%8,%9}, {%0,%1,%2,%3};"
        : "+f"(c[0]), "+f"(c[1]), "+f"(c[2]), "+f"(c[3])
        : "r"(a[0]), "r"(a[1]), "r"(a[2]), "r"(a[3]), "r"(b[0]), "r"(b[1]));
}

// ---------------------------------------------------------------------------
// Fused GEMM body (device function; global buffers are bound by the wrappers
// in DEVICE code): C[N x (d1+d2)] = A[N x 64] @ [root(64 x d1) | Wcat(64 x d2)]
// Root cols get +bias -> outRoot (row stride d1). Wcat cols -> outW (stride d2).
// Wcat column w maps to W[(w/dout)*64*dout + k*dout + (w%dout)]  (W is (R,64,dout)).
// 1-D grid: rb = bid % rowBlocks, cb = bid / rowBlocks.
// BM=64, BN=64, K=64 single phase. 256 threads, 8 warps (4m x 2n).
// ---------------------------------------------------------------------------
namespace {
constexpr int SA = 68;   // A smem stride (floats): conflict-free frag loads
constexpr int SB = 72;   // B smem stride
}

__device__ __forceinline__ void gemm_body(
    const float* __restrict__ A, const float* __restrict__ root,
    const float* __restrict__ W, const float* __restrict__ bias,
    float* __restrict__ outRoot, float* __restrict__ outW,
    int d1, int d2, int dout, int reluA, int rowBlocks) {
    __shared__ float Af[64 * SA];   // 17.4 KB
    __shared__ float Bf[64 * SB];   // 18.4 KB

    const int tid = threadIdx.x;
    const int rb = blockIdx.x % rowBlocks;
    const int cb = blockIdx.x / rowBlocks;
    const int dtot = d1 + d2;

    // ---- load A tile (64 x 64) fp32, optional fused relu ----
#pragma unroll
    for (int i = 0; i < 4; ++i) {
        int idx = tid + i * 256;          // float4 index
        int row = idx >> 4, c4 = idx & 15;
        int grow = rb * 64 + row;
        float4 v = make_float4(0.f, 0.f, 0.f, 0.f);
        if (grow < N_NODES)
            v = reinterpret_cast<const float4*>(A)[(size_t)grow * 16 + c4];
        if (reluA) {
            v.x = fmaxf(v.x, 0.f); v.y = fmaxf(v.y, 0.f);
            v.z = fmaxf(v.z, 0.f); v.w = fmaxf(v.w, 0.f);
        }
        *reinterpret_cast<float4*>(&Af[row * SA + c4 * 4]) = v;
    }
    // ---- load B tile (64 x 64) fp32, concat root|Wcat, zero-fill tail ----
#pragma unroll
    for (int i = 0; i < 16; ++i) {
        int idx = tid + i * 256;
        int k = idx >> 6, c = idx & 63;
        int gc = cb * 64 + c;
        float v = 0.f;
        if (gc < d1) {
            v = root[(size_t)k * d1 + gc];
        } else if (gc < dtot) {
            int w = gc - d1;
            int r = w / dout, j = w - r * dout;
            v = W[((size_t)r * 64 + k) * dout + j];
        }
        Bf[k * SB + c] = v;
    }
    __syncthreads();

    const int wid = tid >> 5, lane = tid & 31;
    const int g = lane >> 2, tg = lane & 3;
    const int wm = (wid & 3) * 16;    // warp row offset (4 warps in m)
    const int wn = (wid >> 2) * 32;   // warp col offset (2 warps in n)

    float acc[4][4];
#pragma unroll
    for (int nt = 0; nt < 4; ++nt)
#pragma unroll
        for (int q = 0; q < 4; ++q) acc[nt][q] = 0.f;

#pragma unroll
    for (int ks = 0; ks < 8; ++ks) {
        const int k0 = ks * 8;
        float a0 = Af[(wm + g)     * SA + k0 + tg];
        float a1 = Af[(wm + g + 8) * SA + k0 + tg];
        float a2 = Af[(wm + g)     * SA + k0 + tg + 4];
        float a3 = Af[(wm + g + 8) * SA + k0 + tg + 4];
        uint32_t ah[4], al[4];
        ah[0] = f2tf32(a0); al[0] = __float_as_uint(a0 - __uint_as_float(ah[0]));
        ah[1] = f2tf32(a1); al[1] = __float_as_uint(a1 - __uint_as_float(ah[1]));
        ah[2] = f2tf32(a2); al[2] = __float_as_uint(a2 - __uint_as_float(ah[2]));
        ah[3] = f2tf32(a3); al[3] = __float_as_uint(a3 - __uint_as_float(ah[3]));
        uint32_t bh[4][2], bl[4][2];
#pragma unroll
        for (int nt = 0; nt < 4; ++nt) {
            int c0 = wn + nt * 8 + g;
            float b0 = Bf[(k0 + tg)     * SB + c0];
            float b1v = Bf[(k0 + tg + 4) * SB + c0];
            bh[nt][0] = f2tf32(b0);
            bl[nt][0] = __float_as_uint(b0 - __uint_as_float(bh[nt][0]));
            bh[nt][1] = f2tf32(b1v);
            bl[nt][1] = __float_as_uint(b1v - __uint_as_float(bh[nt][1]));
        }
#pragma unroll
        for (int nt = 0; nt < 4; ++nt) {
            mma_tf32(acc[nt], ah, bh[nt]);   // hi*hi
            mma_tf32(acc[nt], ah, bl[nt]);   // hi*lo
            mma_tf32(acc[nt], al, bh[nt]);   // lo*hi
        }
    }

    // ---- epilogue: root cols (+bias) -> outRoot; W cols -> outW ----
#pragma unroll
    for (int nt = 0; nt < 4; ++nt) {
        int col = wn + nt * 8 + 2 * tg;
        int gc = cb * 64 + col;
        int r0 = rb * 64 + wm + g;
        int r1 = r0 + 8;
        float2 v0 = make_float2(acc[nt][0], acc[nt][1]);
        float2 v1 = make_float2(acc[nt][2], acc[nt][3]);
        if (gc < d1) {
            float bx = bias[gc], by = bias[gc + 1];
            v0.x += bx; v0.y += by; v1.x += bx; v1.y += by;
            if (r0 < N_NODES)
                *reinterpret_cast<float2*>(&outRoot[(size_t)r0 * d1 + gc]) = v0;
            if (r1 < N_NODES)
                *reinterpret_cast<float2*>(&outRoot[(size_t)r1 * d1 + gc]) = v1;
        } else if (gc < dtot) {
            int w = gc - d1;
            if (r0 < N_NODES)
                *reinterpret_cast<float2*>(&outW[(size_t)r0 * d2 + w]) = v0;
            if (r1 < N_NODES)
                *reinterpret_cast<float2*>(&outW[(size_t)r1 * d2 + w]) = v1;
        }
    }
}

// Layer 1: [h1 | xw] = x @ [root1 | W1cat] + b1. Globals bound in device code.
__global__ void __launch_bounds__(256) k_gemm_l1(
    const float* __restrict__ x, const float* __restrict__ W1,
    const float* __restrict__ root1, const float* __restrict__ b1,
    int rowBlocks) {
    gemm_body(x, root1, W1, b1, g_h1, g_agg, 64, 1024, 64, 0, rowBlocks);
}

// Layer 2: [oacc | hw] = relu(h1) @ [root2 | W2cat] + b2 (oacc in g_cnt storage).
__global__ void __launch_bounds__(256) k_gemm_l2(
    const float* __restrict__ W2, const float* __restrict__ root2,
    const float* __restrict__ b2, int rowBlocks) {
    gemm_body(g_h1, root2, W2, b2, reinterpret_cast<float*>(g_cnt), g_agg,
              16, 256, 16, 1, rowBlocks);
}

// ---------------------------------------------------------------------------
__device__ __forceinline__ void red_add_v4(float* addr, float4 v) {
    asm volatile("red.global.add.v4.f32 [%0], {%1, %2, %3, %4};"
                 :: "l"(addr), "f"(v.x), "f"(v.y), "f"(v.z), "f"(v.w)
                 : "memory");
}

// 16 threads/edge: gather xw[src, r] (64 floats from g_agg), weight,
// RED into h1[dst] (L2-resident; holds the root term from the GEMM).
__global__ void k_scatter1(const int* __restrict__ src, const int* __restrict__ dst,
                           const int* __restrict__ et, int E) {
    long long gid = (long long)blockIdx.x * blockDim.x + threadIdx.x;
    int e = (int)(gid >> 4);
    int lane = (int)(gid & 15);
    if (e >= E) return;
    int s = __ldg(src + e), d = __ldg(dst + e), r = __ldg(et + e);
    float w = g_inv[r * N_NODES + d];
    float4 v = *reinterpret_cast<const float4*>(
        &g_agg[(size_t)s * KBIG + r * 64 + lane * 4]);
    red_add_v4(&g_h1[(size_t)d * D + lane * 4],
               make_float4(v.x * w, v.y * w, v.z * w, v.w * w));
}

// 4 threads/edge: gather hw[src, r] (16 floats from g_agg head), weight,
// RED into oacc[dst] = (float*)g_cnt (L2-resident; holds the root term).
__global__ void k_scatter2(const int* __restrict__ src, const int* __restrict__ dst,
                           const int* __restrict__ et, int E) {
    long long gid = (long long)blockIdx.x * blockDim.x + threadIdx.x;
    int e = (int)(gid >> 2);
    int lane = (int)(gid & 3);
    if (e >= E) return;
    int s = __ldg(src + e), d = __ldg(dst + e), r = __ldg(et + e);
    float w = g_inv[r * N_NODES + d];
    float4 v = *reinterpret_cast<const float4*>(
        &g_agg[(size_t)s * 256 + r * 16 + lane * 4]);
    red_add_v4(&reinterpret_cast<float*>(g_cnt)[(size_t)d * 16 + lane * 4],
               make_float4(v.x * w, v.y * w, v.z * w, v.w * w));
}

// relu + log_softmax over 16 classes; reads oacc (g_cnt storage), writes d_out
// with plain stores only. One thread per row.
__global__ void k_final(float* __restrict__ out) {
    int row = blockIdx.x * blockDim.x + threadIdx.x;
    if (row >= N_NODES) return;
    float v[16];
    const float4* p = reinterpret_cast<const float4*>(
        &reinterpret_cast<const float*>(g_cnt)[(size_t)row * 16]);
#pragma unroll
    for (int q = 0; q < 4; ++q) {
        float4 t = p[q];
        v[q * 4 + 0] = fmaxf(t.x, 0.f);
        v[q * 4 + 1] = fmaxf(t.y, 0.f);
        v[q * 4 + 2] = fmaxf(t.z, 0.f);
        v[q * 4 + 3] = fmaxf(t.w, 0.f);
    }
    float m = -1e30f;
#pragma unroll
    for (int j = 0; j < 16; ++j) m = fmaxf(m, v[j]);
    float s = 0.f;
#pragma unroll
    for (int j = 0; j < 16; ++j) s += expf(v[j] - m);
    float ls = m + logf(s);
    float4* q4 = reinterpret_cast<float4*>(&out[(size_t)row * 16]);
#pragma unroll
    for (int q = 0; q < 4; ++q)
        q4[q] = make_float4(v[q * 4 + 0] - ls, v[q * 4 + 1] - ls,
                            v[q * 4 + 2] - ls, v[q * 4 + 3] - ls);
}

// ---------------------------------------------------------------------------
extern "C" void kernel_launch(void* const* d_in, const int* in_sizes, int n_in,
                              void* d_out, int out_size) {
    const float* x     = (const float*)d_in[0];
    const int*   ei    = (const int*)d_in[1];
    const int*   et    = (const int*)d_in[2];
    const float* W1    = (const float*)d_in[3];
    const float* root1 = (const float*)d_in[4];
    const float* b1    = (const float*)d_in[5];
    const float* W2    = (const float*)d_in[6];
    const float* root2 = (const float*)d_in[7];
    const float* b2    = (const float*)d_in[8];
    float* out = (float*)d_out;

    const int E = in_sizes[2];
    const int* src = ei;
    const int* dst = ei + E;

    const int t = 256;
    const int gRN = (R * N_NODES + t - 1) / t;
    const int rowBlocks = (N_NODES + 63) / 64;
    const int gS1 = (int)(((long long)E * 16 + t - 1) / t);
    const int gS2 = (int)(((long long)E * 4 + t - 1) / t);

    // counts + inverse (shared by both layers); g_cnt is dead after k_inv
    k_zero_cnt<<<gRN, t>>>();
    k_count<<<(E + t - 1) / t, t>>>(dst, et, E);
    k_inv<<<gRN, t>>>();

    // layer 1: [h1 | xw] = x @ [root1 | W1cat] + b1; scatter messages into h1
    k_gemm_l1<<<rowBlocks * 17, t>>>(x, W1, root1, b1, rowBlocks);
    k_scatter1<<<gS1, t>>>(src, dst, et, E);

    // layer 2: [oacc | hw] = relu(h1) @ [root2 | W2cat] + b2 (oacc in g_cnt)
    k_gemm_l2<<<rowBlocks * 5, t>>>(W2, root2, b2, rowBlocks);
    k_scatter2<<<gS2, t>>>(src, dst, et, E);
    k_final<<<(N_NODES + t - 1) / t, t>>>(out);
}